// round 1
// baseline (speedup 1.0000x reference)
#include <cuda_runtime.h>

// Problem constants
#define BB   4
#define TT   2048
#define HH   16
#define SD   64
#define EE   1024
#define NROWS (BB*TT*HH)            // 131072 (b,t,h) rows of 64
#define QK_SCALE 0.17677669529663687f  // 1 / 1024^0.25

// Scratch (device globals — no allocation allowed)
__device__ float g_q [BB*HH*TT*SD];   // [b,h,t,s]
__device__ float g_k [BB*HH*TT*SD];
__device__ float g_v [BB*HH*TT*SD];
__device__ float g_ao[BB*HH*TT*SD];   // attention output [b,h,t,s]

// ---------------------------------------------------------------------------
// Kernel 1: QKV projections. x is [b,t,h,s] == flat [131072][64] row-major.
// Each block: 64 rows. y = x_row @ W^T, W is [64 out][64 in].
// ---------------------------------------------------------------------------
__global__ __launch_bounds__(256) void qkv_kernel(
    const float* __restrict__ x,
    const float* __restrict__ Wk,
    const float* __restrict__ Wq,
    const float* __restrict__ Wv)
{
    __shared__ float Xs[64 * 64];
    __shared__ float Ws[64 * 64];   // row-rotated to dodge bank conflicts

    const int tid = threadIdx.x;
    const int ty = tid >> 4;        // 0..15 -> owns rows ty*4..ty*4+3
    const int tx = tid & 15;        // 0..15 -> owns cols tx*4..tx*4+3
    const int row0 = blockIdx.x * 64;

    for (int idx = tid; idx < 4096; idx += 256)
        Xs[idx] = x[(long)(row0) * 64 + idx];

    const float* Wlist[3] = {Wq, Wk, Wv};
    const float  scl [3]  = {QK_SCALE, QK_SCALE, 1.0f};
    float* outs[3];
    outs[0] = g_q; outs[1] = g_k; outs[2] = g_v;

    for (int mm = 0; mm < 3; mm++) {
        __syncthreads();   // Xs ready (mm==0) / previous Ws no longer read
        const float* W = Wlist[mm];
        for (int idx = tid; idx < 4096; idx += 256) {
            int r = idx >> 6, c = idx & 63;
            Ws[r * 64 + ((c + r) & 63)] = W[idx];
        }
        __syncthreads();

        float acc[4][4];
        #pragma unroll
        for (int i = 0; i < 4; i++)
            #pragma unroll
            for (int j = 0; j < 4; j++) acc[i][j] = 0.f;

        #pragma unroll 8
        for (int kk = 0; kk < 64; kk++) {
            float a[4], w[4];
            #pragma unroll
            for (int i = 0; i < 4; i++) a[i] = Xs[(ty * 4 + i) * 64 + kk];
            #pragma unroll
            for (int j = 0; j < 4; j++) {
                int r = tx * 4 + j;
                w[j] = Ws[r * 64 + ((kk + r) & 63)];
            }
            #pragma unroll
            for (int i = 0; i < 4; i++)
                #pragma unroll
                for (int j = 0; j < 4; j++)
                    acc[i][j] += a[i] * w[j];
        }

        float s = scl[mm];
        float* o = outs[mm];
        #pragma unroll
        for (int i = 0; i < 4; i++) {
            int r = row0 + ty * 4 + i;            // (b,t,h) flattened
            int b = r >> 15;                      // / (2048*16)
            int t = (r >> 4) & 2047;
            int h = r & 15;
            long obase = (((long)(b * HH + h)) * TT + t) * SD;
            #pragma unroll
            for (int j = 0; j < 4; j++)
                o[obase + tx * 4 + j] = acc[i][j] * s;
        }
    }
}

// ---------------------------------------------------------------------------
// Kernel 2: flash attention. grid = (T/64, B*H). BM=BN=64, online softmax.
// Score tile and P·V tile both via 4x4 register tiling on a 16x16 thread grid.
// P reuses the K smem buffer. Row state replicated across each 16-lane group.
// ---------------------------------------------------------------------------
__global__ __launch_bounds__(256) void attn_kernel()
{
    __shared__ float Qs [64 * 64];
    __shared__ float KPs[64 * 64];   // K tile, then P tile (row-rotated)
    __shared__ float Vs [64 * 64];

    const int tid = threadIdx.x;
    const int ty = tid >> 4;
    const int tx = tid & 15;
    const int qt = blockIdx.x;
    const int bh = blockIdx.y;

    const float* qb = g_q + (long)bh * TT * SD;
    const float* kb = g_k + (long)bh * TT * SD;
    const float* vb = g_v + (long)bh * TT * SD;

    for (int idx = tid; idx < 4096; idx += 256)
        Qs[idx] = qb[qt * 4096 + idx];

    float m[4], l[4], o[4][4];
    #pragma unroll
    for (int i = 0; i < 4; i++) {
        m[i] = -1e30f; l[i] = 0.f;
        #pragma unroll
        for (int j = 0; j < 4; j++) o[i][j] = 0.f;
    }

    for (int kt = 0; kt < TT / 64; kt++) {
        __syncthreads();   // prev P reads done / Qs ready
        for (int idx = tid; idx < 4096; idx += 256) {
            int r = idx >> 6, c = idx & 63;
            KPs[r * 64 + ((c + r) & 63)] = kb[kt * 4096 + idx];
            Vs[idx]                      = vb[kt * 4096 + idx];
        }
        __syncthreads();

        // S = Q K^T (64x64)
        float s[4][4];
        #pragma unroll
        for (int i = 0; i < 4; i++)
            #pragma unroll
            for (int j = 0; j < 4; j++) s[i][j] = 0.f;

        #pragma unroll 8
        for (int kk = 0; kk < 64; kk++) {
            float a[4], w[4];
            #pragma unroll
            for (int i = 0; i < 4; i++) a[i] = Qs[(ty * 4 + i) * 64 + kk];
            #pragma unroll
            for (int j = 0; j < 4; j++) {
                int r = tx * 4 + j;
                w[j] = KPs[r * 64 + ((kk + r) & 63)];
            }
            #pragma unroll
            for (int i = 0; i < 4; i++)
                #pragma unroll
                for (int j = 0; j < 4; j++)
                    s[i][j] += a[i] * w[j];
        }

        // online softmax: row max / sum across the 16-lane row group
        float p[4][4], corr[4];
        #pragma unroll
        for (int i = 0; i < 4; i++) {
            float rm = fmaxf(fmaxf(s[i][0], s[i][1]), fmaxf(s[i][2], s[i][3]));
            #pragma unroll
            for (int off = 8; off >= 1; off >>= 1)
                rm = fmaxf(rm, __shfl_xor_sync(0xffffffffu, rm, off));
            float mn = fmaxf(m[i], rm);
            corr[i] = __expf(m[i] - mn);
            float rs = 0.f;
            #pragma unroll
            for (int j = 0; j < 4; j++) {
                p[i][j] = __expf(s[i][j] - mn);
                rs += p[i][j];
            }
            #pragma unroll
            for (int off = 8; off >= 1; off >>= 1)
                rs += __shfl_xor_sync(0xffffffffu, rs, off);
            l[i] = l[i] * corr[i] + rs;
            m[i] = mn;
            #pragma unroll
            for (int j = 0; j < 4; j++) o[i][j] *= corr[i];
        }

        __syncthreads();   // everyone done reading K tile
        #pragma unroll
        for (int i = 0; i < 4; i++) {
            int r = ty * 4 + i;
            #pragma unroll
            for (int j = 0; j < 4; j++)
                KPs[r * 64 + ((tx * 4 + j + r) & 63)] = p[i][j];
        }
        __syncthreads();

        // O += P V
        #pragma unroll 8
        for (int j = 0; j < 64; j++) {
            float a[4], w[4];
            #pragma unroll
            for (int i = 0; i < 4; i++) {
                int r = ty * 4 + i;
                a[i] = KPs[r * 64 + ((j + r) & 63)];
            }
            #pragma unroll
            for (int c = 0; c < 4; c++) w[c] = Vs[j * 64 + tx * 4 + c];
            #pragma unroll
            for (int i = 0; i < 4; i++)
                #pragma unroll
                for (int c = 0; c < 4; c++)
                    o[i][c] += a[i] * w[c];
        }
    }

    float* ob = g_ao + (long)bh * TT * SD;
    #pragma unroll
    for (int i = 0; i < 4; i++) {
        float inv = 1.0f / l[i];
        #pragma unroll
        for (int j = 0; j < 4; j++)
            ob[(qt * 64 + ty * 4 + i) * 64 + tx * 4 + j] = o[i][j] * inv;
    }
}

// ---------------------------------------------------------------------------
// Kernel 3: unify. out[b*T+t][n] = sum_k A[row][k]*Wu[n][k] + bu[n],
// A read from g_ao [b,h,t,s] with permutation folded into addressing.
// ---------------------------------------------------------------------------
__global__ __launch_bounds__(256) void unify_kernel(
    const float* __restrict__ Wu,
    const float* __restrict__ bu,
    float* __restrict__ out)
{
    __shared__ float As[64 * 32];
    __shared__ float Bs[64 * 32];

    const int tid = threadIdx.x;
    const int ty = tid >> 4;
    const int tx = tid & 15;
    const int row0 = blockIdx.y * 64;
    const int col0 = blockIdx.x * 64;
    const int b  = row0 >> 11;      // / 2048  (tiles never straddle b)
    const int t0 = row0 & 2047;

    float acc[4][4];
    #pragma unroll
    for (int i = 0; i < 4; i++)
        #pragma unroll
        for (int j = 0; j < 4; j++) acc[i][j] = 0.f;

    for (int kt = 0; kt < EE / 32; kt++) {
        __syncthreads();
        const int h = kt >> 1;
        const int sbase = (kt & 1) << 5;
        const long abase = (long)b * (HH * TT * SD) + (long)h * (TT * SD);
        for (int idx = tid; idx < 2048; idx += 256) {
            int r = idx >> 5, c = idx & 31;
            As[idx] = g_ao[abase + (long)(t0 + r) * SD + sbase + c];
            Bs[r * 32 + ((c + r) & 31)] = Wu[(long)(col0 + r) * EE + kt * 32 + c];
        }
        __syncthreads();

        #pragma unroll 8
        for (int kk = 0; kk < 32; kk++) {
            float a[4], w[4];
            #pragma unroll
            for (int i = 0; i < 4; i++) a[i] = As[(ty * 4 + i) * 32 + kk];
            #pragma unroll
            for (int j = 0; j < 4; j++) {
                int r = tx * 4 + j;
                w[j] = Bs[r * 32 + ((kk + r) & 31)];
            }
            #pragma unroll
            for (int i = 0; i < 4; i++)
                #pragma unroll
                for (int j = 0; j < 4; j++)
                    acc[i][j] += a[i] * w[j];
        }
    }

    #pragma unroll
    for (int i = 0; i < 4; i++)
        #pragma unroll
        for (int j = 0; j < 4; j++)
            out[(long)(row0 + ty * 4 + i) * EE + col0 + tx * 4 + j] =
                acc[i][j] + bu[col0 + tx * 4 + j];
}

// ---------------------------------------------------------------------------
extern "C" void kernel_launch(void* const* d_in, const int* in_sizes, int n_in,
                              void* d_out, int out_size)
{
    const float* x  = (const float*)d_in[0];
    const float* Wk = (const float*)d_in[1];
    const float* Wq = (const float*)d_in[2];
    const float* Wv = (const float*)d_in[3];
    const float* Wu = (const float*)d_in[4];
    const float* bu = (const float*)d_in[5];
    float* out = (float*)d_out;

    qkv_kernel<<<NROWS / 64, 256>>>(x, Wk, Wq, Wv);
    attn_kernel<<<dim3(TT / 64, BB * HH), 256>>>();
    unify_kernel<<<dim3(EE / 64, (BB * TT) / 64), 256>>>(Wu, bu, out);
}

// round 2
// speedup vs baseline: 1.2556x; 1.2556x over previous
#include <cuda_runtime.h>

// Problem constants
#define BB   4
#define TT   2048
#define HH   16
#define SD   64
#define EE   1024
#define NROWS (BB*TT*HH)               // 131072 rows of 64
#define QK_SCALE 0.17677669529663687f  // 1 / 1024^0.25

// Scratch (device globals — no allocation allowed)
__device__ float g_q [BB*HH*TT*SD];   // [b,h,t,s]
__device__ float g_k [BB*HH*TT*SD];
__device__ float g_v [BB*HH*TT*SD];
__device__ float g_ao[BB*HH*TT*SD];   // attention output [b,h,t,s]

// Swizzled float4 slot for a 64x64 tile stored as [64 rows][16 float4]:
// element group c4 (0..15) of row r lives at r*16 + (c4 ^ (r>>2)).
// For the B-operand access pattern (rows 4*tx+j, fixed c4=k4) this spreads
// the 16 tx-lanes over 16 distinct bank groups -> conflict-free LDS.128.
#define SWZ(r, c4) (((r) << 4) + ((c4) ^ (((r) >> 2) & 15)))

#define DOT4(acc, A, W) \
    acc += (A).x * (W).x + (A).y * (W).y + (A).z * (W).z + (A).w * (W).w;

// ---------------------------------------------------------------------------
// Kernel 1: QKV projections. x is [b,t,h,s] == flat [131072][64] row-major.
// Each block: 64 rows. y = x_row @ W^T, W is [64 out][64 in].
// ---------------------------------------------------------------------------
__global__ __launch_bounds__(256) void qkv_kernel(
    const float* __restrict__ x,
    const float* __restrict__ Wk,
    const float* __restrict__ Wq,
    const float* __restrict__ Wv)
{
    __shared__ float4 Xs[64 * 16];   // unswizzled (row-broadcast reads)
    __shared__ float4 Ws[64 * 16];   // swizzled

    const int tid = threadIdx.x;
    const int ty = tid >> 4;
    const int tx = tid & 15;
    const int row0 = blockIdx.x * 64;

    const float4* xg = (const float4*)(x + (long)row0 * 64);
    #pragma unroll
    for (int i = 0; i < 4; i++) Xs[tid + 256 * i] = xg[tid + 256 * i];

    const float* Wlist[3] = {Wq, Wk, Wv};
    const float  scl [3]  = {QK_SCALE, QK_SCALE, 1.0f};
    float* outs[3];
    outs[0] = g_q; outs[1] = g_k; outs[2] = g_v;

    for (int mm = 0; mm < 3; mm++) {
        __syncthreads();   // Xs ready / previous Ws no longer read
        const float4* Wg = (const float4*)Wlist[mm];
        #pragma unroll
        for (int ii = 0; ii < 4; ii++) {
            int i = tid + 256 * ii;
            Ws[SWZ(i >> 4, i & 15)] = Wg[i];
        }
        __syncthreads();

        float acc[4][4];
        #pragma unroll
        for (int i = 0; i < 4; i++)
            #pragma unroll
            for (int j = 0; j < 4; j++) acc[i][j] = 0.f;

        #pragma unroll 4
        for (int k4 = 0; k4 < 16; k4++) {
            float4 a[4], w[4];
            #pragma unroll
            for (int i = 0; i < 4; i++) a[i] = Xs[(ty * 4 + i) * 16 + k4];
            #pragma unroll
            for (int j = 0; j < 4; j++) w[j] = Ws[(tx * 4 + j) * 16 + (k4 ^ tx)];
            #pragma unroll
            for (int i = 0; i < 4; i++)
                #pragma unroll
                for (int j = 0; j < 4; j++)
                    DOT4(acc[i][j], a[i], w[j]);
        }

        const float s = scl[mm];
        float* o = outs[mm];
        #pragma unroll
        for (int i = 0; i < 4; i++) {
            int r = row0 + ty * 4 + i;            // (b,t,h) flattened
            int b = r >> 15;
            int t = (r >> 4) & 2047;
            int h = r & 15;
            long obase = (((long)(b * HH + h)) * TT + t) * SD;
            float4 v4 = make_float4(acc[i][0] * s, acc[i][1] * s,
                                    acc[i][2] * s, acc[i][3] * s);
            *(float4*)&o[obase + tx * 4] = v4;
        }
    }
}

// ---------------------------------------------------------------------------
// Kernel 2: flash attention. grid = (T/64, B*H). BM=BN=64, online softmax.
// All smem traffic is LDS.128 / STS.128. P reuses the swizzled K buffer.
// ---------------------------------------------------------------------------
__global__ __launch_bounds__(256) void attn_kernel()
{
    __shared__ float4 Qs[64 * 16];   // unswizzled
    __shared__ float4 KP[64 * 16];   // swizzled: K tile, then P tile
    __shared__ float4 Vs[64 * 16];   // unswizzled

    const int tid = threadIdx.x;
    const int ty = tid >> 4;
    const int tx = tid & 15;
    const int qt = blockIdx.x;
    const int bh = blockIdx.y;

    const float* qb = g_q + (long)bh * TT * SD;
    const float* kb = g_k + (long)bh * TT * SD;
    const float* vb = g_v + (long)bh * TT * SD;

    const float4* qg = (const float4*)(qb + qt * 4096);
    #pragma unroll
    for (int i = 0; i < 4; i++) Qs[tid + 256 * i] = qg[tid + 256 * i];

    float m[4], l[4], o[4][4];
    #pragma unroll
    for (int i = 0; i < 4; i++) {
        m[i] = -1e30f; l[i] = 0.f;
        #pragma unroll
        for (int j = 0; j < 4; j++) o[i][j] = 0.f;
    }

    for (int kt = 0; kt < TT / 64; kt++) {
        __syncthreads();   // prev P/V reads done; Qs ready on first iter
        const float4* kg = (const float4*)(kb + kt * 4096);
        const float4* vg = (const float4*)(vb + kt * 4096);
        #pragma unroll
        for (int ii = 0; ii < 4; ii++) {
            int i = tid + 256 * ii;
            KP[SWZ(i >> 4, i & 15)] = kg[i];
            Vs[i]                   = vg[i];
        }
        __syncthreads();

        // S = Q K^T (64x64)
        float s[4][4];
        #pragma unroll
        for (int i = 0; i < 4; i++)
            #pragma unroll
            for (int j = 0; j < 4; j++) s[i][j] = 0.f;

        #pragma unroll 4
        for (int k4 = 0; k4 < 16; k4++) {
            float4 a[4], w[4];
            #pragma unroll
            for (int i = 0; i < 4; i++) a[i] = Qs[(ty * 4 + i) * 16 + k4];
            #pragma unroll
            for (int j = 0; j < 4; j++) w[j] = KP[(tx * 4 + j) * 16 + (k4 ^ tx)];
            #pragma unroll
            for (int i = 0; i < 4; i++)
                #pragma unroll
                for (int j = 0; j < 4; j++)
                    DOT4(s[i][j], a[i], w[j]);
        }

        // online softmax: row max / sum across the 16-lane row group
        float p[4][4];
        #pragma unroll
        for (int i = 0; i < 4; i++) {
            float rm = fmaxf(fmaxf(s[i][0], s[i][1]), fmaxf(s[i][2], s[i][3]));
            #pragma unroll
            for (int off = 8; off >= 1; off >>= 1)
                rm = fmaxf(rm, __shfl_xor_sync(0xffffffffu, rm, off));
            float mn = fmaxf(m[i], rm);
            float corr = __expf(m[i] - mn);
            float rs = 0.f;
            #pragma unroll
            for (int j = 0; j < 4; j++) {
                p[i][j] = __expf(s[i][j] - mn);
                rs += p[i][j];
            }
            #pragma unroll
            for (int off = 8; off >= 1; off >>= 1)
                rs += __shfl_xor_sync(0xffffffffu, rs, off);
            l[i] = l[i] * corr + rs;
            m[i] = mn;
            #pragma unroll
            for (int j = 0; j < 4; j++) o[i][j] *= corr;
        }

        __syncthreads();   // everyone done reading K from KP
        #pragma unroll
        for (int i = 0; i < 4; i++) {
            int r = ty * 4 + i;
            KP[(r << 4) + (tx ^ (r >> 2))] =
                make_float4(p[i][0], p[i][1], p[i][2], p[i][3]);
        }
        __syncthreads();

        // O += P V
        #pragma unroll 4
        for (int j4 = 0; j4 < 16; j4++) {
            float4 a[4], w[4];
            #pragma unroll
            for (int i = 0; i < 4; i++) {
                int r = ty * 4 + i;
                a[i] = KP[(r << 4) + (j4 ^ (r >> 2))];
            }
            #pragma unroll
            for (int jj = 0; jj < 4; jj++) w[jj] = Vs[(j4 * 4 + jj) * 16 + tx];
            #pragma unroll
            for (int i = 0; i < 4; i++) {
                float4 A = a[i];
                o[i][0] += A.x * w[0].x + A.y * w[1].x + A.z * w[2].x + A.w * w[3].x;
                o[i][1] += A.x * w[0].y + A.y * w[1].y + A.z * w[2].y + A.w * w[3].y;
                o[i][2] += A.x * w[0].z + A.y * w[1].z + A.z * w[2].z + A.w * w[3].z;
                o[i][3] += A.x * w[0].w + A.y * w[1].w + A.z * w[2].w + A.w * w[3].w;
            }
        }
    }

    float* ob = g_ao + (long)bh * TT * SD;
    #pragma unroll
    for (int i = 0; i < 4; i++) {
        float inv = 1.0f / l[i];
        float4 v4 = make_float4(o[i][0] * inv, o[i][1] * inv,
                                o[i][2] * inv, o[i][3] * inv);
        *(float4*)&ob[(qt * 64 + ty * 4 + i) * 64 + tx * 4] = v4;
    }
}

// ---------------------------------------------------------------------------
// Kernel 3: unify. out[b*T+t][n] = sum_k A[row][k]*Wu[n][k] + bu[n].
// k-tile = 64 = one head, so each A tile is a contiguous 64x64 block of g_ao.
// ---------------------------------------------------------------------------
__global__ __launch_bounds__(256) void unify_kernel(
    const float* __restrict__ Wu,
    const float* __restrict__ bu,
    float* __restrict__ out)
{
    __shared__ float4 As[64 * 16];   // unswizzled
    __shared__ float4 Bs[64 * 16];   // swizzled

    const int tid = threadIdx.x;
    const int ty = tid >> 4;
    const int tx = tid & 15;
    const int row0 = blockIdx.y * 64;
    const int col0 = blockIdx.x * 64;
    const int b  = row0 >> 11;      // tiles never straddle b
    const int t0 = row0 & 2047;

    float acc[4][4];
    #pragma unroll
    for (int i = 0; i < 4; i++)
        #pragma unroll
        for (int j = 0; j < 4; j++) acc[i][j] = 0.f;

    for (int h = 0; h < HH; h++) {
        __syncthreads();
        const float4* ag = (const float4*)(g_ao + ((long)(b * HH + h)) * TT * SD
                                                + (long)t0 * SD);
        const float4* wg = (const float4*)(Wu + (long)col0 * EE + h * 64);
        #pragma unroll
        for (int ii = 0; ii < 4; ii++) {
            int i = tid + 256 * ii;
            int r = i >> 4, c4 = i & 15;
            As[i] = ag[i];
            Bs[SWZ(r, c4)] = wg[r * (EE / 4) + c4];
        }
        __syncthreads();

        #pragma unroll 4
        for (int k4 = 0; k4 < 16; k4++) {
            float4 a[4], w[4];
            #pragma unroll
            for (int i = 0; i < 4; i++) a[i] = As[(ty * 4 + i) * 16 + k4];
            #pragma unroll
            for (int j = 0; j < 4; j++) w[j] = Bs[(tx * 4 + j) * 16 + (k4 ^ tx)];
            #pragma unroll
            for (int i = 0; i < 4; i++)
                #pragma unroll
                for (int j = 0; j < 4; j++)
                    DOT4(acc[i][j], a[i], w[j]);
        }
    }

    const float4 bias = *(const float4*)&bu[col0 + tx * 4];
    #pragma unroll
    for (int i = 0; i < 4; i++) {
        float4 v4 = make_float4(acc[i][0] + bias.x, acc[i][1] + bias.y,
                                acc[i][2] + bias.z, acc[i][3] + bias.w);
        *(float4*)&out[(long)(row0 + ty * 4 + i) * EE + col0 + tx * 4] = v4;
    }
}

// ---------------------------------------------------------------------------
extern "C" void kernel_launch(void* const* d_in, const int* in_sizes, int n_in,
                              void* d_out, int out_size)
{
    const float* x  = (const float*)d_in[0];
    const float* Wk = (const float*)d_in[1];
    const float* Wq = (const float*)d_in[2];
    const float* Wv = (const float*)d_in[3];
    const float* Wu = (const float*)d_in[4];
    const float* bu = (const float*)d_in[5];
    float* out = (float*)d_out;

    qkv_kernel<<<NROWS / 64, 256>>>(x, Wk, Wq, Wv);
    attn_kernel<<<dim3(TT / 64, BB * HH), 256>>>();
    unify_kernel<<<dim3(EE / 64, (BB * TT) / 64), 256>>>(Wu, bu, out);
}

// round 3
// speedup vs baseline: 1.3268x; 1.0567x over previous
#include <cuda_runtime.h>

// Problem constants
#define BB   4
#define TT   2048
#define HH   16
#define SD   64
#define EE   1024
#define NROWS (BB*TT*HH)               // 131072 rows of 64
#define QK_SCALE 0.17677669529663687f  // 1 / 1024^0.25

// Scratch (device globals — no allocation allowed)
__device__ float g_q [BB*HH*TT*SD];   // [b,h,t,s]
__device__ float g_k [BB*HH*TT*SD];
__device__ float g_v [BB*HH*TT*SD];
__device__ float g_ao[BB*HH*TT*SD];   // attention output [b,h,t,s]

// Swizzled float4 slot for a 64x64 tile stored as [64 rows][16 float4]:
// element group c4 (0..15) of row r lives at r*16 + (c4 ^ (r>>2)).
// For the B-operand access pattern (rows 4*tx+j, fixed c4=k4) this spreads
// the 16 tx-lanes over 16 distinct bank groups -> conflict-free LDS.128.
#define SWZ(r, c4) (((r) << 4) + ((c4) ^ (((r) >> 2) & 15)))

#define DOT4(acc, A, W) \
    acc += (A).x * (W).x + (A).y * (W).y + (A).z * (W).z + (A).w * (W).w;

// ---------------------------------------------------------------------------
// Kernel 1: QKV projections. x is [b,t,h,s] == flat [131072][64] row-major.
// Each block: 64 rows. y = x_row @ W^T, W is [64 out][64 in].
// ---------------------------------------------------------------------------
__global__ __launch_bounds__(256) void qkv_kernel(
    const float* __restrict__ x,
    const float* __restrict__ Wk,
    const float* __restrict__ Wq,
    const float* __restrict__ Wv)
{
    __shared__ float4 Xs[64 * 16];   // unswizzled (row-broadcast reads)
    __shared__ float4 Ws[64 * 16];   // swizzled

    const int tid = threadIdx.x;
    const int ty = tid >> 4;
    const int tx = tid & 15;
    const int row0 = blockIdx.x * 64;

    const float4* xg = (const float4*)(x + (long)row0 * 64);
    #pragma unroll
    for (int i = 0; i < 4; i++) Xs[tid + 256 * i] = xg[tid + 256 * i];

    const float* Wlist[3] = {Wq, Wk, Wv};
    const float  scl [3]  = {QK_SCALE, QK_SCALE, 1.0f};
    float* outs[3];
    outs[0] = g_q; outs[1] = g_k; outs[2] = g_v;

    for (int mm = 0; mm < 3; mm++) {
        __syncthreads();   // Xs ready / previous Ws no longer read
        const float4* Wg = (const float4*)Wlist[mm];
        #pragma unroll
        for (int ii = 0; ii < 4; ii++) {
            int i = tid + 256 * ii;
            Ws[SWZ(i >> 4, i & 15)] = Wg[i];
        }
        __syncthreads();

        float acc[4][4];
        #pragma unroll
        for (int i = 0; i < 4; i++)
            #pragma unroll
            for (int j = 0; j < 4; j++) acc[i][j] = 0.f;

        #pragma unroll 4
        for (int k4 = 0; k4 < 16; k4++) {
            float4 a[4], w[4];
            #pragma unroll
            for (int i = 0; i < 4; i++) a[i] = Xs[(ty * 4 + i) * 16 + k4];
            #pragma unroll
            for (int j = 0; j < 4; j++) w[j] = Ws[(tx * 4 + j) * 16 + (k4 ^ tx)];
            #pragma unroll
            for (int i = 0; i < 4; i++)
                #pragma unroll
                for (int j = 0; j < 4; j++)
                    DOT4(acc[i][j], a[i], w[j]);
        }

        const float s = scl[mm];
        float* o = outs[mm];
        #pragma unroll
        for (int i = 0; i < 4; i++) {
            int r = row0 + ty * 4 + i;            // (b,t,h) flattened
            int b = r >> 15;
            int t = (r >> 4) & 2047;
            int h = r & 15;
            long obase = (((long)(b * HH + h)) * TT + t) * SD;
            float4 v4 = make_float4(acc[i][0] * s, acc[i][1] * s,
                                    acc[i][2] * s, acc[i][3] * s);
            *(float4*)&o[obase + tx * 4] = v4;
        }
    }
}

// ---------------------------------------------------------------------------
// Kernel 2: flash attention. grid = (T/64, B*H). BM=BN=64, online softmax.
// All smem traffic is LDS.128 / STS.128. P reuses the swizzled K buffer.
// ---------------------------------------------------------------------------
__global__ __launch_bounds__(256) void attn_kernel()
{
    __shared__ float4 Qs[64 * 16];   // unswizzled
    __shared__ float4 KP[64 * 16];   // swizzled: K tile, then P tile
    __shared__ float4 Vs[64 * 16];   // unswizzled

    const int tid = threadIdx.x;
    const int ty = tid >> 4;
    const int tx = tid & 15;
    const int qt = blockIdx.x;
    const int bh = blockIdx.y;

    const float* qb = g_q + (long)bh * TT * SD;
    const float* kb = g_k + (long)bh * TT * SD;
    const float* vb = g_v + (long)bh * TT * SD;

    const float4* qg = (const float4*)(qb + qt * 4096);
    #pragma unroll
    for (int i = 0; i < 4; i++) Qs[tid + 256 * i] = qg[tid + 256 * i];

    float m[4], l[4], o[4][4];
    #pragma unroll
    for (int i = 0; i < 4; i++) {
        m[i] = -1e30f; l[i] = 0.f;
        #pragma unroll
        for (int j = 0; j < 4; j++) o[i][j] = 0.f;
    }

    for (int kt = 0; kt < TT / 64; kt++) {
        __syncthreads();   // prev P/V reads done; Qs ready on first iter
        const float4* kg = (const float4*)(kb + kt * 4096);
        const float4* vg = (const float4*)(vb + kt * 4096);
        #pragma unroll
        for (int ii = 0; ii < 4; ii++) {
            int i = tid + 256 * ii;
            KP[SWZ(i >> 4, i & 15)] = kg[i];
            Vs[i]                   = vg[i];
        }
        __syncthreads();

        // S = Q K^T (64x64)
        float s[4][4];
        #pragma unroll
        for (int i = 0; i < 4; i++)
            #pragma unroll
            for (int j = 0; j < 4; j++) s[i][j] = 0.f;

        #pragma unroll 4
        for (int k4 = 0; k4 < 16; k4++) {
            float4 a[4], w[4];
            #pragma unroll
            for (int i = 0; i < 4; i++) a[i] = Qs[(ty * 4 + i) * 16 + k4];
            #pragma unroll
            for (int j = 0; j < 4; j++) w[j] = KP[(tx * 4 + j) * 16 + (k4 ^ tx)];
            #pragma unroll
            for (int i = 0; i < 4; i++)
                #pragma unroll
                for (int j = 0; j < 4; j++)
                    DOT4(s[i][j], a[i], w[j]);
        }

        // online softmax: row max / sum across the 16-lane row group
        float p[4][4];
        #pragma unroll
        for (int i = 0; i < 4; i++) {
            float rm = fmaxf(fmaxf(s[i][0], s[i][1]), fmaxf(s[i][2], s[i][3]));
            #pragma unroll
            for (int off = 8; off >= 1; off >>= 1)
                rm = fmaxf(rm, __shfl_xor_sync(0xffffffffu, rm, off));
            float mn = fmaxf(m[i], rm);
            float corr = __expf(m[i] - mn);
            float rs = 0.f;
            #pragma unroll
            for (int j = 0; j < 4; j++) {
                p[i][j] = __expf(s[i][j] - mn);
                rs += p[i][j];
            }
            #pragma unroll
            for (int off = 8; off >= 1; off >>= 1)
                rs += __shfl_xor_sync(0xffffffffu, rs, off);
            l[i] = l[i] * corr + rs;
            m[i] = mn;
            #pragma unroll
            for (int j = 0; j < 4; j++) o[i][j] *= corr;
        }

        __syncthreads();   // everyone done reading K from KP
        #pragma unroll
        for (int i = 0; i < 4; i++) {
            int r = ty * 4 + i;
            KP[(r << 4) + (tx ^ (r >> 2))] =
                make_float4(p[i][0], p[i][1], p[i][2], p[i][3]);
        }
        __syncthreads();

        // O += P V
        #pragma unroll 4
        for (int j4 = 0; j4 < 16; j4++) {
            float4 a[4], w[4];
            #pragma unroll
            for (int i = 0; i < 4; i++) {
                int r = ty * 4 + i;
                a[i] = KP[(r << 4) + (j4 ^ (r >> 2))];
            }
            #pragma unroll
            for (int jj = 0; jj < 4; jj++) w[jj] = Vs[(j4 * 4 + jj) * 16 + tx];
            #pragma unroll
            for (int i = 0; i < 4; i++) {
                float4 A = a[i];
                o[i][0] += A.x * w[0].x + A.y * w[1].x + A.z * w[2].x + A.w * w[3].x;
                o[i][1] += A.x * w[0].y + A.y * w[1].y + A.z * w[2].y + A.w * w[3].y;
                o[i][2] += A.x * w[0].z + A.y * w[1].z + A.z * w[2].z + A.w * w[3].z;
                o[i][3] += A.x * w[0].w + A.y * w[1].w + A.z * w[2].w + A.w * w[3].w;
            }
        }
    }

    float* ob = g_ao + (long)bh * TT * SD;
    #pragma unroll
    for (int i = 0; i < 4; i++) {
        float inv = 1.0f / l[i];
        float4 v4 = make_float4(o[i][0] * inv, o[i][1] * inv,
                                o[i][2] * inv, o[i][3] * inv);
        *(float4*)&ob[(qt * 64 + ty * 4 + i) * 64 + tx * 4] = v4;
    }
}

// ---------------------------------------------------------------------------
// Kernel 3: unify. out[b*T+t][n] = sum_k A[row][k]*Wu[n][k] + bu[n].
// k-tile = 64 = one head, so each A tile is a contiguous 64x64 block of g_ao.
// ---------------------------------------------------------------------------
__global__ __launch_bounds__(256) void unify_kernel(
    const float* __restrict__ Wu,
    const float* __restrict__ bu,
    float* __restrict__ out)
{
    __shared__ float4 As[64 * 16];   // unswizzled
    __shared__ float4 Bs[64 * 16];   // swizzled

    const int tid = threadIdx.x;
    const int ty = tid >> 4;
    const int tx = tid & 15;
    const int row0 = blockIdx.y * 64;
    const int col0 = blockIdx.x * 64;
    const int b  = row0 >> 11;      // tiles never straddle b
    const int t0 = row0 & 2047;

    float acc[4][4];
    #pragma unroll
    for (int i = 0; i < 4; i++)
        #pragma unroll
        for (int j = 0; j < 4; j++) acc[i][j] = 0.f;

    for (int h = 0; h < HH; h++) {
        __syncthreads();
        const float4* ag = (const float4*)(g_ao + ((long)(b * HH + h)) * TT * SD
                                                + (long)t0 * SD);
        const float4* wg = (const float4*)(Wu + (long)col0 * EE + h * 64);
        #pragma unroll
        for (int ii = 0; ii < 4; ii++) {
            int i = tid + 256 * ii;
            int r = i >> 4, c4 = i & 15;
            As[i] = ag[i];
            Bs[SWZ(r, c4)] = wg[r * (EE / 4) + c4];
        }
        __syncthreads();

        #pragma unroll 4
        for (int k4 = 0; k4 < 16; k4++) {
            float4 a[4], w[4];
            #pragma unroll
            for (int i = 0; i < 4; i++) a[i] = As[(ty * 4 + i) * 16 + k4];
            #pragma unroll
            for (int j = 0; j < 4; j++) w[j] = Bs[(tx * 4 + j) * 16 + (k4 ^ tx)];
            #pragma unroll
            for (int i = 0; i < 4; i++)
                #pragma unroll
                for (int j = 0; j < 4; j++)
                    DOT4(acc[i][j], a[i], w[j]);
        }
    }

    const float4 bias = *(const float4*)&bu[col0 + tx * 4];
    #pragma unroll
    for (int i = 0; i < 4; i++) {
        float4 v4 = make_float4(acc[i][0] + bias.x, acc[i][1] + bias.y,
                                acc[i][2] + bias.z, acc[i][3] + bias.w);
        *(float4*)&out[(long)(row0 + ty * 4 + i) * EE + col0 + tx * 4] = v4;
    }
}

// ---------------------------------------------------------------------------
extern "C" void kernel_launch(void* const* d_in, const int* in_sizes, int n_in,
                              void* d_out, int out_size)
{
    const float* x  = (const float*)d_in[0];
    const float* Wk = (const float*)d_in[1];
    const float* Wq = (const float*)d_in[2];
    const float* Wv = (const float*)d_in[3];
    const float* Wu = (const float*)d_in[4];
    const float* bu = (const float*)d_in[5];
    float* out = (float*)d_out;

    qkv_kernel<<<NROWS / 64, 256>>>(x, Wk, Wq, Wv);
    attn_kernel<<<dim3(TT / 64, BB * HH), 256>>>();
    unify_kernel<<<dim3(EE / 64, (BB * TT) / 64), 256>>>(Wu, bu, out);
}

// round 4
// speedup vs baseline: 1.3272x; 1.0003x over previous
#include <cuda_runtime.h>

// Problem constants
#define BB   4
#define TT   2048
#define HH   16
#define SD   64
#define EE   1024
#define NROWS (BB*TT*HH)               // 131072 rows of 64
#define QK_SCALE 0.17677669529663687f  // 1 / 1024^0.25

// Scratch (device globals — no allocation allowed)
__device__ float g_q [BB*HH*TT*SD];   // [b,h,t,s]
__device__ float g_k [BB*HH*TT*SD];
__device__ float g_v [BB*HH*TT*SD];
__device__ float g_ao[BB*HH*TT*SD];   // attention output [b,h,t,s]

// Swizzled float4 slot for a 64x64 tile stored as [64 rows][16 float4]:
// element group c4 (0..15) of row r lives at r*16 + (c4 ^ (r>>2)).
// For the B-operand access pattern (rows 4*tx+j, fixed c4=k4) this spreads
// the 16 tx-lanes over 16 distinct bank groups -> conflict-free LDS.128.
#define SWZ(r, c4) (((r) << 4) + ((c4) ^ (((r) >> 2) & 15)))

#define DOT4(acc, A, W) \
    acc += (A).x * (W).x + (A).y * (W).y + (A).z * (W).z + (A).w * (W).w;

// ---------------------------------------------------------------------------
// Kernel 1: QKV projections. x is [b,t,h,s] == flat [131072][64] row-major.
// Each block: 64 rows. y = x_row @ W^T, W is [64 out][64 in].
// ---------------------------------------------------------------------------
__global__ __launch_bounds__(256) void qkv_kernel(
    const float* __restrict__ x,
    const float* __restrict__ Wk,
    const float* __restrict__ Wq,
    const float* __restrict__ Wv)
{
    __shared__ float4 Xs[64 * 16];   // unswizzled (row-broadcast reads)
    __shared__ float4 Ws[64 * 16];   // swizzled

    const int tid = threadIdx.x;
    const int ty = tid >> 4;
    const int tx = tid & 15;
    const int row0 = blockIdx.x * 64;

    const float4* xg = (const float4*)(x + (long)row0 * 64);
    #pragma unroll
    for (int i = 0; i < 4; i++) Xs[tid + 256 * i] = xg[tid + 256 * i];

    const float* Wlist[3] = {Wq, Wk, Wv};
    const float  scl [3]  = {QK_SCALE, QK_SCALE, 1.0f};
    float* outs[3];
    outs[0] = g_q; outs[1] = g_k; outs[2] = g_v;

    for (int mm = 0; mm < 3; mm++) {
        __syncthreads();   // Xs ready / previous Ws no longer read
        const float4* Wg = (const float4*)Wlist[mm];
        #pragma unroll
        for (int ii = 0; ii < 4; ii++) {
            int i = tid + 256 * ii;
            Ws[SWZ(i >> 4, i & 15)] = Wg[i];
        }
        __syncthreads();

        float acc[4][4];
        #pragma unroll
        for (int i = 0; i < 4; i++)
            #pragma unroll
            for (int j = 0; j < 4; j++) acc[i][j] = 0.f;

        #pragma unroll 4
        for (int k4 = 0; k4 < 16; k4++) {
            float4 a[4], w[4];
            #pragma unroll
            for (int i = 0; i < 4; i++) a[i] = Xs[(ty * 4 + i) * 16 + k4];
            #pragma unroll
            for (int j = 0; j < 4; j++) w[j] = Ws[(tx * 4 + j) * 16 + (k4 ^ tx)];
            #pragma unroll
            for (int i = 0; i < 4; i++)
                #pragma unroll
                for (int j = 0; j < 4; j++)
                    DOT4(acc[i][j], a[i], w[j]);
        }

        const float s = scl[mm];
        float* o = outs[mm];
        #pragma unroll
        for (int i = 0; i < 4; i++) {
            int r = row0 + ty * 4 + i;            // (b,t,h) flattened
            int b = r >> 15;
            int t = (r >> 4) & 2047;
            int h = r & 15;
            long obase = (((long)(b * HH + h)) * TT + t) * SD;
            float4 v4 = make_float4(acc[i][0] * s, acc[i][1] * s,
                                    acc[i][2] * s, acc[i][3] * s);
            *(float4*)&o[obase + tx * 4] = v4;
        }
    }
}

// ---------------------------------------------------------------------------
// Kernel 2: flash attention. grid = (T/64, B*H). BM=BN=64, online softmax.
// All smem traffic is LDS.128 / STS.128. P reuses the swizzled K buffer.
// ---------------------------------------------------------------------------
__global__ __launch_bounds__(256) void attn_kernel()
{
    __shared__ float4 Qs[64 * 16];   // unswizzled
    __shared__ float4 KP[64 * 16];   // swizzled: K tile, then P tile
    __shared__ float4 Vs[64 * 16];   // unswizzled

    const int tid = threadIdx.x;
    const int ty = tid >> 4;
    const int tx = tid & 15;
    const int qt = blockIdx.x;
    const int bh = blockIdx.y;

    const float* qb = g_q + (long)bh * TT * SD;
    const float* kb = g_k + (long)bh * TT * SD;
    const float* vb = g_v + (long)bh * TT * SD;

    const float4* qg = (const float4*)(qb + qt * 4096);
    #pragma unroll
    for (int i = 0; i < 4; i++) Qs[tid + 256 * i] = qg[tid + 256 * i];

    float m[4], l[4], o[4][4];
    #pragma unroll
    for (int i = 0; i < 4; i++) {
        m[i] = -1e30f; l[i] = 0.f;
        #pragma unroll
        for (int j = 0; j < 4; j++) o[i][j] = 0.f;
    }

    for (int kt = 0; kt < TT / 64; kt++) {
        __syncthreads();   // prev P/V reads done; Qs ready on first iter
        const float4* kg = (const float4*)(kb + kt * 4096);
        const float4* vg = (const float4*)(vb + kt * 4096);
        #pragma unroll
        for (int ii = 0; ii < 4; ii++) {
            int i = tid + 256 * ii;
            KP[SWZ(i >> 4, i & 15)] = kg[i];
            Vs[i]                   = vg[i];
        }
        __syncthreads();

        // S = Q K^T (64x64)
        float s[4][4];
        #pragma unroll
        for (int i = 0; i < 4; i++)
            #pragma unroll
            for (int j = 0; j < 4; j++) s[i][j] = 0.f;

        #pragma unroll 4
        for (int k4 = 0; k4 < 16; k4++) {
            float4 a[4], w[4];
            #pragma unroll
            for (int i = 0; i < 4; i++) a[i] = Qs[(ty * 4 + i) * 16 + k4];
            #pragma unroll
            for (int j = 0; j < 4; j++) w[j] = KP[(tx * 4 + j) * 16 + (k4 ^ tx)];
            #pragma unroll
            for (int i = 0; i < 4; i++)
                #pragma unroll
                for (int j = 0; j < 4; j++)
                    DOT4(s[i][j], a[i], w[j]);
        }

        // online softmax: row max / sum across the 16-lane row group
        float p[4][4];
        #pragma unroll
        for (int i = 0; i < 4; i++) {
            float rm = fmaxf(fmaxf(s[i][0], s[i][1]), fmaxf(s[i][2], s[i][3]));
            #pragma unroll
            for (int off = 8; off >= 1; off >>= 1)
                rm = fmaxf(rm, __shfl_xor_sync(0xffffffffu, rm, off));
            float mn = fmaxf(m[i], rm);
            float corr = __expf(m[i] - mn);
            float rs = 0.f;
            #pragma unroll
            for (int j = 0; j < 4; j++) {
                p[i][j] = __expf(s[i][j] - mn);
                rs += p[i][j];
            }
            #pragma unroll
            for (int off = 8; off >= 1; off >>= 1)
                rs += __shfl_xor_sync(0xffffffffu, rs, off);
            l[i] = l[i] * corr + rs;
            m[i] = mn;
            #pragma unroll
            for (int j = 0; j < 4; j++) o[i][j] *= corr;
        }

        __syncthreads();   // everyone done reading K from KP
        #pragma unroll
        for (int i = 0; i < 4; i++) {
            int r = ty * 4 + i;
            KP[(r << 4) + (tx ^ (r >> 2))] =
                make_float4(p[i][0], p[i][1], p[i][2], p[i][3]);
        }
        __syncthreads();

        // O += P V
        #pragma unroll 4
        for (int j4 = 0; j4 < 16; j4++) {
            float4 a[4], w[4];
            #pragma unroll
            for (int i = 0; i < 4; i++) {
                int r = ty * 4 + i;
                a[i] = KP[(r << 4) + (j4 ^ (r >> 2))];
            }
            #pragma unroll
            for (int jj = 0; jj < 4; jj++) w[jj] = Vs[(j4 * 4 + jj) * 16 + tx];
            #pragma unroll
            for (int i = 0; i < 4; i++) {
                float4 A = a[i];
                o[i][0] += A.x * w[0].x + A.y * w[1].x + A.z * w[2].x + A.w * w[3].x;
                o[i][1] += A.x * w[0].y + A.y * w[1].y + A.z * w[2].y + A.w * w[3].y;
                o[i][2] += A.x * w[0].z + A.y * w[1].z + A.z * w[2].z + A.w * w[3].z;
                o[i][3] += A.x * w[0].w + A.y * w[1].w + A.z * w[2].w + A.w * w[3].w;
            }
        }
    }

    float* ob = g_ao + (long)bh * TT * SD;
    #pragma unroll
    for (int i = 0; i < 4; i++) {
        float inv = 1.0f / l[i];
        float4 v4 = make_float4(o[i][0] * inv, o[i][1] * inv,
                                o[i][2] * inv, o[i][3] * inv);
        *(float4*)&ob[(qt * 64 + ty * 4 + i) * 64 + tx * 4] = v4;
    }
}

// ---------------------------------------------------------------------------
// Kernel 3: unify. out[b*T+t][n] = sum_k A[row][k]*Wu[n][k] + bu[n].
// k-tile = 64 = one head, so each A tile is a contiguous 64x64 block of g_ao.
// ---------------------------------------------------------------------------
__global__ __launch_bounds__(256) void unify_kernel(
    const float* __restrict__ Wu,
    const float* __restrict__ bu,
    float* __restrict__ out)
{
    __shared__ float4 As[64 * 16];   // unswizzled
    __shared__ float4 Bs[64 * 16];   // swizzled

    const int tid = threadIdx.x;
    const int ty = tid >> 4;
    const int tx = tid & 15;
    const int row0 = blockIdx.y * 64;
    const int col0 = blockIdx.x * 64;
    const int b  = row0 >> 11;      // tiles never straddle b
    const int t0 = row0 & 2047;

    float acc[4][4];
    #pragma unroll
    for (int i = 0; i < 4; i++)
        #pragma unroll
        for (int j = 0; j < 4; j++) acc[i][j] = 0.f;

    for (int h = 0; h < HH; h++) {
        __syncthreads();
        const float4* ag = (const float4*)(g_ao + ((long)(b * HH + h)) * TT * SD
                                                + (long)t0 * SD);
        const float4* wg = (const float4*)(Wu + (long)col0 * EE + h * 64);
        #pragma unroll
        for (int ii = 0; ii < 4; ii++) {
            int i = tid + 256 * ii;
            int r = i >> 4, c4 = i & 15;
            As[i] = ag[i];
            Bs[SWZ(r, c4)] = wg[r * (EE / 4) + c4];
        }
        __syncthreads();

        #pragma unroll 4
        for (int k4 = 0; k4 < 16; k4++) {
            float4 a[4], w[4];
            #pragma unroll
            for (int i = 0; i < 4; i++) a[i] = As[(ty * 4 + i) * 16 + k4];
            #pragma unroll
            for (int j = 0; j < 4; j++) w[j] = Bs[(tx * 4 + j) * 16 + (k4 ^ tx)];
            #pragma unroll
            for (int i = 0; i < 4; i++)
                #pragma unroll
                for (int j = 0; j < 4; j++)
                    DOT4(acc[i][j], a[i], w[j]);
        }
    }

    const float4 bias = *(const float4*)&bu[col0 + tx * 4];
    #pragma unroll
    for (int i = 0; i < 4; i++) {
        float4 v4 = make_float4(acc[i][0] + bias.x, acc[i][1] + bias.y,
                                acc[i][2] + bias.z, acc[i][3] + bias.w);
        *(float4*)&out[(long)(row0 + ty * 4 + i) * EE + col0 + tx * 4] = v4;
    }
}

// ---------------------------------------------------------------------------
extern "C" void kernel_launch(void* const* d_in, const int* in_sizes, int n_in,
                              void* d_out, int out_size)
{
    const float* x  = (const float*)d_in[0];
    const float* Wk = (const float*)d_in[1];
    const float* Wq = (const float*)d_in[2];
    const float* Wv = (const float*)d_in[3];
    const float* Wu = (const float*)d_in[4];
    const float* bu = (const float*)d_in[5];
    float* out = (float*)d_out;

    qkv_kernel<<<NROWS / 64, 256>>>(x, Wk, Wq, Wv);
    attn_kernel<<<dim3(TT / 64, BB * HH), 256>>>();
    unify_kernel<<<dim3(EE / 64, (BB * TT) / 64), 256>>>(Wu, bu, out);
}

// round 5
// speedup vs baseline: 3.5042x; 2.6403x over previous
#include <cuda_runtime.h>
#include <cuda_bf16.h>
#include <cstdint>

// Problem constants
#define BB   4
#define TT   2048
#define HH   16
#define SD   64
#define EE   1024
#define NROWS (BB*TT*HH)               // 131072 rows of 64
#define QK_SCALE 0.17677669529663687f  // 1 / 1024^0.25

// Scratch (device globals — no allocation allowed)
// q/k/v stored as split bf16 (hi + lo residual), layout [b,h,t,s]
__device__ __nv_bfloat16 g_qh[NROWS*SD], g_ql[NROWS*SD];
__device__ __nv_bfloat16 g_kh[NROWS*SD], g_kl[NROWS*SD];
__device__ __nv_bfloat16 g_vh[NROWS*SD], g_vl[NROWS*SD];
__device__ float g_ao[NROWS*SD];       // attention output fp32 [b,h,t,s]

// ---------------------------------------------------------------------------
// helpers
// ---------------------------------------------------------------------------
__device__ __forceinline__ uint32_t smem_u32(const void* p) {
    return (uint32_t)__cvta_generic_to_shared(p);
}
__device__ __forceinline__ void ldsm_x2(uint32_t& r0, uint32_t& r1, uint32_t a) {
    asm volatile("ldmatrix.sync.aligned.m8n8.x2.shared.b16 {%0,%1},[%2];"
                 : "=r"(r0), "=r"(r1) : "r"(a));
}
__device__ __forceinline__ void ldsm_x2_t(uint32_t& r0, uint32_t& r1, uint32_t a) {
    asm volatile("ldmatrix.sync.aligned.m8n8.x2.trans.shared.b16 {%0,%1},[%2];"
                 : "=r"(r0), "=r"(r1) : "r"(a));
}
__device__ __forceinline__ void ldsm_x4(uint32_t* r, uint32_t a) {
    asm volatile("ldmatrix.sync.aligned.m8n8.x4.shared.b16 {%0,%1,%2,%3},[%4];"
                 : "=r"(r[0]), "=r"(r[1]), "=r"(r[2]), "=r"(r[3]) : "r"(a));
}
// D += A * B (m16n8k16, bf16 in, f32 accum)
__device__ __forceinline__ void mma16816(float* d, const uint32_t* a,
                                         uint32_t b0, uint32_t b1) {
    asm volatile("mma.sync.aligned.m16n8k16.row.col.f32.bf16.bf16.f32 "
                 "{%0,%1,%2,%3},{%4,%5,%6,%7},{%8,%9},{%0,%1,%2,%3};"
                 : "+f"(d[0]), "+f"(d[1]), "+f"(d[2]), "+f"(d[3])
                 : "r"(a[0]), "r"(a[1]), "r"(a[2]), "r"(a[3]), "r"(b0), "r"(b1));
}
__device__ __forceinline__ uint32_t cvt2_bf16(float x, float y) {
    __nv_bfloat162 h = __floats2bfloat162_rn(x, y);
    return *reinterpret_cast<uint32_t*>(&h);
}
__device__ __forceinline__ uint32_t cvt2_bf16_lo(float x, float y, uint32_t hi) {
    __nv_bfloat162 h = *reinterpret_cast<__nv_bfloat162*>(&hi);
    return cvt2_bf16(x - __low2float(h), y - __high2float(h));
}

// ---------------------------------------------------------------------------
// Kernel 1: QKV projections (fp32 SIMT, already at FFMA roofline).
// x is [b,t,h,s] == flat [131072][64]. Outputs split-bf16 q/k/v in [b,h,t,s].
// ---------------------------------------------------------------------------
#define SWZ4(r, c4) (((r) << 4) + ((c4) ^ (((r) >> 2) & 15)))
#define DOT4(acc, A, W) \
    acc += (A).x * (W).x + (A).y * (W).y + (A).z * (W).z + (A).w * (W).w;

__global__ __launch_bounds__(256) void qkv_kernel(
    const float* __restrict__ x,
    const float* __restrict__ Wk,
    const float* __restrict__ Wq,
    const float* __restrict__ Wv)
{
    __shared__ float4 Xs[64 * 16];
    __shared__ float4 Ws[64 * 16];

    const int tid = threadIdx.x;
    const int ty = tid >> 4;
    const int tx = tid & 15;
    const int row0 = blockIdx.x * 64;

    const float4* xg = (const float4*)(x + (long)row0 * 64);
    #pragma unroll
    for (int i = 0; i < 4; i++) Xs[tid + 256 * i] = xg[tid + 256 * i];

    const float* Wlist[3] = {Wq, Wk, Wv};
    const float  scl [3]  = {QK_SCALE, QK_SCALE, 1.0f};
    __nv_bfloat16* outh[3] = {g_qh, g_kh, g_vh};
    __nv_bfloat16* outl[3] = {g_ql, g_kl, g_vl};

    for (int mm = 0; mm < 3; mm++) {
        __syncthreads();
        const float4* Wg = (const float4*)Wlist[mm];
        #pragma unroll
        for (int ii = 0; ii < 4; ii++) {
            int i = tid + 256 * ii;
            Ws[SWZ4(i >> 4, i & 15)] = Wg[i];
        }
        __syncthreads();

        float acc[4][4];
        #pragma unroll
        for (int i = 0; i < 4; i++)
            #pragma unroll
            for (int j = 0; j < 4; j++) acc[i][j] = 0.f;

        #pragma unroll 4
        for (int k4 = 0; k4 < 16; k4++) {
            float4 a[4], w[4];
            #pragma unroll
            for (int i = 0; i < 4; i++) a[i] = Xs[(ty * 4 + i) * 16 + k4];
            #pragma unroll
            for (int j = 0; j < 4; j++) w[j] = Ws[(tx * 4 + j) * 16 + (k4 ^ tx)];
            #pragma unroll
            for (int i = 0; i < 4; i++)
                #pragma unroll
                for (int j = 0; j < 4; j++)
                    DOT4(acc[i][j], a[i], w[j]);
        }

        const float s = scl[mm];
        __nv_bfloat16* oh = outh[mm];
        __nv_bfloat16* ol = outl[mm];
        #pragma unroll
        for (int i = 0; i < 4; i++) {
            int r = row0 + ty * 4 + i;            // (b,t,h) flattened
            int b = r >> 15;
            int t = (r >> 4) & 2047;
            int h = r & 15;
            long obase = (((long)(b * HH + h)) * TT + t) * SD + tx * 4;
            float y0 = acc[i][0] * s, y1 = acc[i][1] * s;
            float y2 = acc[i][2] * s, y3 = acc[i][3] * s;
            uint32_t h01 = cvt2_bf16(y0, y1), h23 = cvt2_bf16(y2, y3);
            uint32_t l01 = cvt2_bf16_lo(y0, y1, h01), l23 = cvt2_bf16_lo(y2, y3, h23);
            *(uint32_t*)&oh[obase]     = h01;
            *(uint32_t*)&oh[obase + 2] = h23;
            *(uint32_t*)&ol[obase]     = l01;
            *(uint32_t*)&ol[obase + 2] = l23;
        }
    }
}

// ---------------------------------------------------------------------------
// Kernel 2: flash attention on tensor cores (split-bf16 HMMA).
// grid=(T/64, B*H), block=128 (4 warps). Warp w owns q-rows w*16..+15, all 64 n.
// Q fragments persistent in registers. K/V tiles in smem (XOR-granule swizzle).
// P kept in registers (acc layout == A-fragment layout).
// ---------------------------------------------------------------------------
__global__ __launch_bounds__(128) void attn_kernel()
{
    __shared__ alignas(16) __nv_bfloat16 sKh[64*64], sKl[64*64];
    __shared__ alignas(16) __nv_bfloat16 sVh[64*64], sVl[64*64];

    const int tid  = threadIdx.x;
    const int lane = tid & 31;
    const int warp = tid >> 5;
    const int qt   = blockIdx.x;
    const int bh   = blockIdx.y;
    const long base = (long)bh * TT * SD;

    const int t4  = lane & 3;          // col pair within n8 / k16
    const int r16 = lane >> 2;         // row within 8-row group
    const int rl  = lane & 7;
    const int sub = (lane >> 3) & 1;

    // --- persistent Q fragments (hi + lo), 4 k-chunks ---
    uint32_t QAh[4][4], QAl[4][4];
    {
        const __nv_bfloat16* qh = g_qh + base;
        const __nv_bfloat16* ql = g_ql + base;
        const int r0 = qt * 64 + warp * 16 + r16;
        #pragma unroll
        for (int kc = 0; kc < 4; kc++) {
            int c0 = kc * 16 + 2 * t4;
            QAh[kc][0] = *(const uint32_t*)(qh + (long)r0      * 64 + c0);
            QAh[kc][1] = *(const uint32_t*)(qh + (long)(r0 + 8)* 64 + c0);
            QAh[kc][2] = *(const uint32_t*)(qh + (long)r0      * 64 + c0 + 8);
            QAh[kc][3] = *(const uint32_t*)(qh + (long)(r0 + 8)* 64 + c0 + 8);
            QAl[kc][0] = *(const uint32_t*)(ql + (long)r0      * 64 + c0);
            QAl[kc][1] = *(const uint32_t*)(ql + (long)(r0 + 8)* 64 + c0);
            QAl[kc][2] = *(const uint32_t*)(ql + (long)r0      * 64 + c0 + 8);
            QAl[kc][3] = *(const uint32_t*)(ql + (long)(r0 + 8)* 64 + c0 + 8);
        }
    }

    float O[8][4];
    #pragma unroll
    for (int j = 0; j < 8; j++)
        #pragma unroll
        for (int c = 0; c < 4; c++) O[j][c] = 0.f;
    float mrow[2] = {-1e30f, -1e30f};
    float lrow[2] = {0.f, 0.f};

    const uint32_t aKh = smem_u32(sKh), aKl = smem_u32(sKl);
    const uint32_t aVh = smem_u32(sVh), aVl = smem_u32(sVl);

    for (int kt = 0; kt < TT / 64; kt++) {
        __syncthreads();
        {   // load K/V tiles (bf16 hi/lo) with 16B-granule XOR swizzle
            const uint4* gkh = (const uint4*)(g_kh + base + kt * 4096);
            const uint4* gkl = (const uint4*)(g_kl + base + kt * 4096);
            const uint4* gvh = (const uint4*)(g_vh + base + kt * 4096);
            const uint4* gvl = (const uint4*)(g_vl + base + kt * 4096);
            #pragma unroll
            for (int it = 0; it < 4; it++) {
                int idx = it * 128 + tid;           // granule id 0..511
                int row = idx >> 3, g = idx & 7;
                int dst = row * 8 + (g ^ (row & 7));
                ((uint4*)sKh)[dst] = gkh[idx];
                ((uint4*)sKl)[dst] = gkl[idx];
                ((uint4*)sVh)[dst] = gvh[idx];
                ((uint4*)sVl)[dst] = gvl[idx];
            }
        }
        __syncthreads();

        // ---- S = Q K^T ----
        float S[8][4];
        #pragma unroll
        for (int j = 0; j < 8; j++)
            #pragma unroll
            for (int c = 0; c < 4; c++) S[j][c] = 0.f;

        #pragma unroll
        for (int kc = 0; kc < 4; kc++) {
            #pragma unroll
            for (int j = 0; j < 8; j++) {
                uint32_t off = (uint32_t)((8 * j + rl) * 128 +
                                          (((2 * kc + sub) ^ rl) * 16));
                uint32_t b0h, b1h, b0l, b1l;
                ldsm_x2(b0h, b1h, aKh + off);
                ldsm_x2(b0l, b1l, aKl + off);
                mma16816(S[j], QAh[kc], b0h, b1h);
                mma16816(S[j], QAh[kc], b0l, b1l);
                mma16816(S[j], QAl[kc], b0h, b1h);
            }
        }

        // ---- online softmax (warp-local) ----
        #pragma unroll
        for (int hh = 0; hh < 2; hh++) {
            float mx = -1e30f;
            #pragma unroll
            for (int j = 0; j < 8; j++)
                mx = fmaxf(mx, fmaxf(S[j][2*hh], S[j][2*hh+1]));
            mx = fmaxf(mx, __shfl_xor_sync(0xffffffffu, mx, 1));
            mx = fmaxf(mx, __shfl_xor_sync(0xffffffffu, mx, 2));
            float mn   = fmaxf(mrow[hh], mx);
            float corr = __expf(mrow[hh] - mn);
            float sum = 0.f;
            #pragma unroll
            for (int j = 0; j < 8; j++) {
                S[j][2*hh]   = __expf(S[j][2*hh]   - mn);
                S[j][2*hh+1] = __expf(S[j][2*hh+1] - mn);
                sum += S[j][2*hh] + S[j][2*hh+1];
            }
            sum += __shfl_xor_sync(0xffffffffu, sum, 1);
            sum += __shfl_xor_sync(0xffffffffu, sum, 2);
            lrow[hh] = lrow[hh] * corr + sum;
            mrow[hh] = mn;
            #pragma unroll
            for (int j = 0; j < 8; j++) {
                O[j][2*hh]   *= corr;
                O[j][2*hh+1] *= corr;
            }
        }

        // ---- P (registers): acc layout -> A-fragment layout ----
        uint32_t PAh[4][4], PAl[4][4];
        #pragma unroll
        for (int nc = 0; nc < 4; nc++) {
            const float* s0 = S[2*nc];
            const float* s1 = S[2*nc+1];
            PAh[nc][0] = cvt2_bf16(s0[0], s0[1]);
            PAh[nc][1] = cvt2_bf16(s0[2], s0[3]);
            PAh[nc][2] = cvt2_bf16(s1[0], s1[1]);
            PAh[nc][3] = cvt2_bf16(s1[2], s1[3]);
            PAl[nc][0] = cvt2_bf16_lo(s0[0], s0[1], PAh[nc][0]);
            PAl[nc][1] = cvt2_bf16_lo(s0[2], s0[3], PAh[nc][1]);
            PAl[nc][2] = cvt2_bf16_lo(s1[0], s1[1], PAh[nc][2]);
            PAl[nc][3] = cvt2_bf16_lo(s1[2], s1[3], PAh[nc][3]);
        }

        // ---- O += P V ----
        #pragma unroll
        for (int nc = 0; nc < 4; nc++) {
            #pragma unroll
            for (int j = 0; j < 8; j++) {
                uint32_t off = (uint32_t)((16 * nc + (lane & 15)) * 128 +
                                          ((j ^ rl) * 16));
                uint32_t v0h, v1h, v0l, v1l;
                ldsm_x2_t(v0h, v1h, aVh + off);
                ldsm_x2_t(v0l, v1l, aVl + off);
                mma16816(O[j], PAh[nc], v0h, v1h);
                mma16816(O[j], PAh[nc], v0l, v1l);
                mma16816(O[j], PAl[nc], v0h, v1h);
            }
        }
    }

    // ---- epilogue ----
    {
        float inv0 = 1.0f / lrow[0];
        float inv1 = 1.0f / lrow[1];
        float* ob = g_ao + base;
        const int r0 = qt * 64 + warp * 16 + r16;
        #pragma unroll
        for (int j = 0; j < 8; j++) {
            int c = 8 * j + 2 * t4;
            float2 v0 = make_float2(O[j][0] * inv0, O[j][1] * inv0);
            float2 v1 = make_float2(O[j][2] * inv1, O[j][3] * inv1);
            *(float2*)&ob[(long)r0      * 64 + c] = v0;
            *(float2*)&ob[(long)(r0 + 8)* 64 + c] = v1;
        }
    }
}

// ---------------------------------------------------------------------------
// Kernel 3: unify GEMM on tensor cores (split-bf16).
// out[row][n] = sum_k A[row][k] * Wu[n][k] + bu[n], A = g_ao permuted
// (k-tile 64 == one head -> contiguous 64x64 block). grid=(16,128), 4 warps.
// ---------------------------------------------------------------------------
__global__ __launch_bounds__(128) void unify_kernel(
    const float* __restrict__ Wu,
    const float* __restrict__ bu,
    float* __restrict__ out)
{
    __shared__ alignas(16) __nv_bfloat16 sAh[64*64], sAl[64*64];
    __shared__ alignas(16) __nv_bfloat16 sWh[64*64], sWl[64*64];

    const int tid  = threadIdx.x;
    const int lane = tid & 31;
    const int warp = tid >> 5;
    const int row0 = blockIdx.y * 64;
    const int col0 = blockIdx.x * 64;
    const int b    = row0 >> 11;       // tiles never straddle b
    const int t0   = row0 & 2047;

    const int t4  = lane & 3;
    const int r16 = lane >> 2;
    const int rl  = lane & 7;
    const int sub  = (lane >> 3) & 1;
    const int half = (lane >> 3) & 1;
    const int kh   = (lane >> 4) & 1;

    float acc[8][4];
    #pragma unroll
    for (int j = 0; j < 8; j++)
        #pragma unroll
        for (int c = 0; c < 4; c++) acc[j][c] = 0.f;

    const uint32_t aAh = smem_u32(sAh), aAl = smem_u32(sAl);
    const uint32_t aWh = smem_u32(sWh), aWl = smem_u32(sWl);

    for (int h = 0; h < HH; h++) {
        __syncthreads();
        {
            const float* ag = g_ao + ((long)(b * HH + h)) * TT * SD + (long)t0 * SD;
            const float* wg = Wu + (long)col0 * EE + h * 64;
            #pragma unroll
            for (int it = 0; it < 4; it++) {
                int idx = it * 128 + tid;       // granule id 0..511
                int row = idx >> 3, g = idx & 7;
                int dst = (row * 8 + (g ^ (row & 7))) * 8;  // element offset

                float4 a0 = *(const float4*)(ag + row * 64 + g * 8);
                float4 a1 = *(const float4*)(ag + row * 64 + g * 8 + 4);
                uint32_t h01 = cvt2_bf16(a0.x, a0.y), h23 = cvt2_bf16(a0.z, a0.w);
                uint32_t h45 = cvt2_bf16(a1.x, a1.y), h67 = cvt2_bf16(a1.z, a1.w);
                *(uint4*)&sAh[dst] = make_uint4(h01, h23, h45, h67);
                *(uint4*)&sAl[dst] = make_uint4(
                    cvt2_bf16_lo(a0.x, a0.y, h01), cvt2_bf16_lo(a0.z, a0.w, h23),
                    cvt2_bf16_lo(a1.x, a1.y, h45), cvt2_bf16_lo(a1.z, a1.w, h67));

                float4 w0 = *(const float4*)(wg + (long)row * EE + g * 8);
                float4 w1 = *(const float4*)(wg + (long)row * EE + g * 8 + 4);
                uint32_t wh01 = cvt2_bf16(w0.x, w0.y), wh23 = cvt2_bf16(w0.z, w0.w);
                uint32_t wh45 = cvt2_bf16(w1.x, w1.y), wh67 = cvt2_bf16(w1.z, w1.w);
                *(uint4*)&sWh[dst] = make_uint4(wh01, wh23, wh45, wh67);
                *(uint4*)&sWl[dst] = make_uint4(
                    cvt2_bf16_lo(w0.x, w0.y, wh01), cvt2_bf16_lo(w0.z, w0.w, wh23),
                    cvt2_bf16_lo(w1.x, w1.y, wh45), cvt2_bf16_lo(w1.z, w1.w, wh67));
            }
        }
        __syncthreads();

        #pragma unroll
        for (int kc = 0; kc < 4; kc++) {
            // A fragments (x4 ldmatrix)
            int arow = warp * 16 + rl + 8 * half;
            uint32_t offA = (uint32_t)(arow * 128 + (((2 * kc + kh) ^ rl) * 16));
            uint32_t Ah[4], Al[4];
            ldsm_x4(Ah, aAh + offA);
            ldsm_x4(Al, aAl + offA);
            #pragma unroll
            for (int j = 0; j < 8; j++) {
                uint32_t offW = (uint32_t)((8 * j + rl) * 128 +
                                           (((2 * kc + sub) ^ rl) * 16));
                uint32_t w0h, w1h, w0l, w1l;
                ldsm_x2(w0h, w1h, aWh + offW);
                ldsm_x2(w0l, w1l, aWl + offW);
                mma16816(acc[j], Ah, w0h, w1h);
                mma16816(acc[j], Ah, w0l, w1l);
                mma16816(acc[j], Al, w0h, w1h);
            }
        }
    }

    // store + bias
    {
        const int r0g = row0 + warp * 16 + r16;
        #pragma unroll
        for (int j = 0; j < 8; j++) {
            int c = col0 + 8 * j + 2 * t4;
            float2 bias = *(const float2*)&bu[c];
            float2 v0 = make_float2(acc[j][0] + bias.x, acc[j][1] + bias.y);
            float2 v1 = make_float2(acc[j][2] + bias.x, acc[j][3] + bias.y);
            *(float2*)&out[(long)r0g      * EE + c] = v0;
            *(float2*)&out[(long)(r0g + 8)* EE + c] = v1;
        }
    }
}

// ---------------------------------------------------------------------------
extern "C" void kernel_launch(void* const* d_in, const int* in_sizes, int n_in,
                              void* d_out, int out_size)
{
    const float* x  = (const float*)d_in[0];
    const float* Wk = (const float*)d_in[1];
    const float* Wq = (const float*)d_in[2];
    const float* Wv = (const float*)d_in[3];
    const float* Wu = (const float*)d_in[4];
    const float* bu = (const float*)d_in[5];
    float* out = (float*)d_out;

    qkv_kernel<<<NROWS / 64, 256>>>(x, Wk, Wq, Wv);
    attn_kernel<<<dim3(TT / 64, BB * HH), 128>>>();
    unify_kernel<<<dim3(EE / 64, (BB * TT) / 64), 128>>>(Wu, bu, out);
}